// round 12
// baseline (speedup 1.0000x reference)
#include <cuda_runtime.h>
#include <cuda_bf16.h>
#include <cuda_fp16.h>
#include <stdint.h>
#include <math.h>

#define NHALF 2048
#define NTOT  4096
#define DDIM  512

#define BM 128
#define BN 128
#define BK 32
#define NCHUNK (DDIM / BK)   // 16
#define NTILE 32
#define NBLK 528             // upper-triangle tiles

#define TPAD 40                      // bf16 per smem tile row (80 B)
#define TILE_B (128 * TPAD * 2)      // 10240 B
#define STAGE_B (2 * TILE_B)         // Ah, Bh only
#define SM_TOTAL (2 * STAGE_B)       // 40960 B (fp16 dist tile overlays)
#define DS_STRIDE 136                // halves per epilogue smem row

#define MARGIN 0.15f
#define RGRID 512                    // refine grid (8 rows per block)

// ---------------- device globals ----------------
__device__ float          g_sq[NTOT];
__device__ float          g_pos[NTOT];
__device__ float          g_neg[NTOT];
__device__ unsigned       g_negmin_bits[NTOT];
__device__ unsigned       g_done;
__device__ __nv_bfloat16  g_hi[NTOT * DDIM];
__device__ __half         g_dist[NTOT * NTOT];   // 32 MB approx dists

// ---------------- helpers ----------------
__device__ __forceinline__ uint32_t smem_u32(const void* p) {
    uint32_t a;
    asm("{ .reg .u64 t; cvta.to.shared.u64 t, %1; cvt.u32.u64 %0, t; }"
        : "=r"(a) : "l"(p));
    return a;
}
__device__ __forceinline__ void cp16(uint32_t dst, const void* src) {
    asm volatile("cp.async.cg.shared.global [%0], [%1], 16;"
                 :: "r"(dst), "l"(src));
}
#define CP_COMMIT() asm volatile("cp.async.commit_group;" ::: "memory")
#define CP_WAIT1()  asm volatile("cp.async.wait_group 1;" ::: "memory")
#define CP_WAIT0()  asm volatile("cp.async.wait_group 0;" ::: "memory")

__device__ __forceinline__ void ldx4(uint32_t* r, uint32_t addr) {
    asm volatile("ldmatrix.sync.aligned.m8n8.x4.shared.b16 {%0,%1,%2,%3}, [%4];"
                 : "=r"(r[0]), "=r"(r[1]), "=r"(r[2]), "=r"(r[3]) : "r"(addr));
}
__device__ __forceinline__ void mma16816(float* d, const uint32_t* a,
                                         const uint32_t* b) {
    asm volatile(
        "mma.sync.aligned.m16n8k16.row.col.f32.bf16.bf16.f32 "
        "{%0,%1,%2,%3}, {%4,%5,%6,%7}, {%8,%9}, {%0,%1,%2,%3};"
        : "+f"(d[0]), "+f"(d[1]), "+f"(d[2]), "+f"(d[3])
        : "r"(a[0]), "r"(a[1]), "r"(a[2]), "r"(a[3]), "r"(b[0]), "r"(b[1]));
}
__device__ __forceinline__ float clamp_dist(float d2) {
    return fmaxf(sqrtf(fmaxf(d2, 1e-14f)), 1e-7f);
}

// ---------------------------------------------------------------------------
// Kernel 1: per-pair sums of squares, exact positive dist, bf16-hi split,
//           scratch reset (negmin bits + done counter)
// ---------------------------------------------------------------------------
__global__ __launch_bounds__(256)
void prep_kernel(const float* __restrict__ h1,
                 const float* __restrict__ h2) {
    const int wid = threadIdx.x >> 5, lane = threadIdx.x & 31;
    const int r = blockIdx.x * 8 + wid;      // 0..2047
    const float* xr = h1 + (size_t)r * DDIM;
    const float* yr = h2 + (size_t)r * DDIM;

    float s1 = 0.0f, s2 = 0.0f, dt = 0.0f;
    #pragma unroll
    for (int u = 0; u < 4; u++) {
        const int fi = lane + 32 * u;
        float4 xv = ((const float4*)xr)[fi];
        float4 yv = ((const float4*)yr)[fi];
        s1 += xv.x * xv.x + xv.y * xv.y + xv.z * xv.z + xv.w * xv.w;
        s2 += yv.x * yv.x + yv.y * yv.y + yv.z * yv.z + yv.w * yv.w;
        dt += xv.x * yv.x + xv.y * yv.y + xv.z * yv.z + xv.w * yv.w;

        size_t bx = (size_t)r * DDIM + 4 * fi;
        __nv_bfloat162* gx = (__nv_bfloat162*)(g_hi + bx);
        gx[0] = __nv_bfloat162(__float2bfloat16(xv.x), __float2bfloat16(xv.y));
        gx[1] = __nv_bfloat162(__float2bfloat16(xv.z), __float2bfloat16(xv.w));
        __nv_bfloat162* gy = (__nv_bfloat162*)(g_hi + bx + (size_t)NHALF * DDIM);
        gy[0] = __nv_bfloat162(__float2bfloat16(yv.x), __float2bfloat16(yv.y));
        gy[1] = __nv_bfloat162(__float2bfloat16(yv.z), __float2bfloat16(yv.w));
    }

    #pragma unroll
    for (int off = 16; off > 0; off >>= 1) {
        s1 += __shfl_xor_sync(0xffffffffu, s1, off);
        s2 += __shfl_xor_sync(0xffffffffu, s2, off);
        dt += __shfl_xor_sync(0xffffffffu, dt, off);
    }

    if (lane == 0) {
        g_sq[r] = s1;
        g_sq[r + NHALF] = s2;
        float pos = clamp_dist(s1 + s2 - 2.0f * dt);
        g_pos[r] = pos;
        g_pos[r + NHALF] = pos;
        g_negmin_bits[r] = 0x7f800000u;
        g_negmin_bits[r + NHALF] = 0x7f800000u;
        if (r == 0) g_done = 0u;
    }
}

// ---------------------------------------------------------------------------
// async-load one pipeline stage (2 tiles of 128 x 32 bf16: Ah, Bh)
// ---------------------------------------------------------------------------
__device__ __forceinline__ void load_stage(uint32_t smb, int stage,
                                           const __nv_bfloat16* ah,
                                           const __nv_bfloat16* bh,
                                           int k0, int tid) {
    const __nv_bfloat16* srcs[2] = {ah, bh};
    uint32_t base = smb + stage * STAGE_B;
    #pragma unroll
    for (int t = 0; t < 2; t++) {
        #pragma unroll
        for (int i = 0; i < 2; i++) {
            int chunk = tid * 2 + i;       // 0..511
            int r = chunk >> 2;            // 0..127
            int c = chunk & 3;             // 16B chunk within 64B row
            cp16(base + t * TILE_B + r * (TPAD * 2) + c * 16,
                 srcs[t] + (size_t)r * DDIM + k0 + c * 8);
        }
    }
}

// ---------------------------------------------------------------------------
// Kernel 2: hi-only bf16 mma.sync X*X^T (upper triangle); stores approx
// distances (fp16) + approx row/col minima via atomicMin
// ---------------------------------------------------------------------------
__global__ __launch_bounds__(256, 2)
void gemm_dist_kernel() {
    extern __shared__ char smem[];
    const uint32_t smb = smem_u32(smem);
    const int tid = threadIdx.x;
    const int wid = tid >> 5, lane = tid & 31;

    // decode upper-triangle tile index
    int t = blockIdx.x;
    int bi = 0;
    while (t >= NTILE - bi) { t -= NTILE - bi; bi++; }
    const int bj = bi + t;
    const int row0 = bi * BM;
    const int col0 = bj * BN;
    const bool isdiag = (bi == bj);

    const __nv_bfloat16* Ah_g = g_hi + (size_t)row0 * DDIM;
    const __nv_bfloat16* Bh_g = g_hi + (size_t)col0 * DDIM;

    // warp tile: 32 (M) x 64 (N)
    const int wm = wid & 3, wn = wid >> 2;
    const int m0 = wm * 32, n0 = wn * 64;

    float acc[2][8][4];
    #pragma unroll
    for (int i = 0; i < 2; i++)
        #pragma unroll
        for (int j = 0; j < 8; j++)
            #pragma unroll
            for (int q = 0; q < 4; q++)
                acc[i][j][q] = 0.0f;

    const int arow = (lane & 7) + ((lane >> 3) & 1) * 8;
    const int acol = (lane >> 4) * 8;
    const int brow = (lane & 7) + ((lane >> 4) << 3);
    const int bcol = ((lane >> 3) & 1) * 8;

    load_stage(smb, 0, Ah_g, Bh_g, 0, tid);
    CP_COMMIT();

    for (int it = 0; it < NCHUNK; it++) {
        if (it + 1 < NCHUNK) {
            load_stage(smb, (it + 1) & 1, Ah_g, Bh_g, (it + 1) * BK, tid);
            CP_COMMIT();
            CP_WAIT1();
        } else {
            CP_WAIT0();
        }
        __syncthreads();

        const uint32_t Ah = smb + (it & 1) * STAGE_B;
        const uint32_t Bh = Ah + TILE_B;

        #pragma unroll
        for (int ks = 0; ks < 2; ks++) {
            const int kb = ks * 16;
            uint32_t ahr[2][4];
            #pragma unroll
            for (int mt = 0; mt < 2; mt++) {
                uint32_t off = (uint32_t)(m0 + mt * 16 + arow) * (TPAD * 2)
                             + (kb + acol) * 2;
                ldx4(ahr[mt], Ah + off);
            }
            #pragma unroll
            for (int p = 0; p < 4; p++) {
                uint32_t off = (uint32_t)(n0 + p * 16 + brow) * (TPAD * 2)
                             + (kb + bcol) * 2;
                uint32_t rh[4];
                ldx4(rh, Bh + off);
                uint32_t b0h[2] = {rh[0], rh[1]}, b1h[2] = {rh[2], rh[3]};
                #pragma unroll
                for (int mt = 0; mt < 2; mt++) {
                    mma16816(acc[mt][2 * p],     ahr[mt], b0h);
                    mma16816(acc[mt][2 * p + 1], ahr[mt], b1h);
                }
            }
        }
        __syncthreads();
    }

    // ------------- epilogue: dist(fp16) into smem tile -------------
    __half* ds = (__half*)smem;
    const int g = lane >> 2;
    const int cl = (lane & 3) * 2;
    #pragma unroll
    for (int mt = 0; mt < 2; mt++) {
        const int rb = m0 + mt * 16 + g;
        #pragma unroll
        for (int nt = 0; nt < 8; nt++) {
            const int cb = n0 + nt * 8 + cl;
            #pragma unroll
            for (int h = 0; h < 2; h++) {
                const int rr = rb + h * 8;
                const float si = g_sq[row0 + rr];
                float d0 = clamp_dist(si + g_sq[col0 + cb]
                                      - 2.0f * acc[mt][nt][2 * h]);
                float d1 = clamp_dist(si + g_sq[col0 + cb + 1]
                                      - 2.0f * acc[mt][nt][2 * h + 1]);
                *(__half2*)&ds[rr * DS_STRIDE + cb] =
                    __floats2half2_rn(d0, d1);
            }
        }
    }
    __syncthreads();

    // store row-orientation block: [row0..][col0..]
    {
        const int rb = tid >> 1, seg = tid & 1;
        const uint4* src = (const uint4*)&ds[rb * DS_STRIDE + seg * 64];
        uint4* dst = (uint4*)&g_dist[(size_t)(row0 + rb) * NTOT + col0 + seg * 64];
        #pragma unroll
        for (int q = 0; q < 8; q++) dst[q] = src[q];
    }
    // store transposed block (off-diagonal only): [col0..][row0..]
    if (!isdiag) {
        const int c = tid >> 1, seg = tid & 1;
        __half v[64];
        #pragma unroll 8
        for (int k = 0; k < 64; k++)
            v[k] = ds[(seg * 64 + k) * DS_STRIDE + c];
        uint4* dst = (uint4*)&g_dist[(size_t)(col0 + c) * NTOT + row0 + seg * 64];
        const uint4* sv = (const uint4*)v;
        #pragma unroll
        for (int q = 0; q < 8; q++) dst[q] = sv[q];
    }

    // approx minima: row pass (tid<128) and col pass (tid>=128)
    const float INF = __int_as_float(0x7f800000);
    if (tid < 128) {
        const int gi = row0 + tid;
        const int partner = gi ^ NHALF;
        float mn = INF;
        #pragma unroll 4
        for (int c = 0; c < 128; c++) {
            const int gj = col0 + c;
            float d = __half2float(ds[tid * DS_STRIDE + c]);
            if (gj != gi && gj != partner) mn = fminf(mn, d);
        }
        atomicMin(&g_negmin_bits[gi], __float_as_uint(mn));
    } else if (!isdiag) {
        const int c = tid - 128;
        const int gj = col0 + c;
        const int partner = gj ^ NHALF;
        float mn = INF;
        #pragma unroll 4
        for (int r = 0; r < 128; r++) {
            const int gi = row0 + r;
            float d = __half2float(ds[r * DS_STRIDE + c]);
            if (gi != gj && gi != partner) mn = fminf(mn, d);
        }
        atomicMin(&g_negmin_bits[gj], __float_as_uint(mn));
    }
}

// ---------------------------------------------------------------------------
// Kernel 3: refine (single candidate pass + exact recompute) + fused finalize
// grid RGRID x 256 (8 warps); warp = one row
// ---------------------------------------------------------------------------
__global__ __launch_bounds__(256)
void refine_kernel(const float* __restrict__ h1,
                   const float* __restrict__ h2,
                   float* __restrict__ out) {
    const int wid = threadIdx.x >> 5, lane = threadIdx.x & 31;
    const int r = blockIdx.x * 8 + wid;          // 0..4095
    const int partner = r ^ NHALF;
    const float INF = __int_as_float(0x7f800000);

    const float thresh = __uint_as_float(g_negmin_bits[r]) + MARGIN;
    const __half* row = g_dist + (size_t)r * NTOT;

    // preload this row's fp32 data (16 dims per lane)
    const float* xr = (r < NHALF) ? h1 + (size_t)r * DDIM
                                  : h2 + (size_t)(r - NHALF) * DDIM;
    float4 x4[4];
    #pragma unroll
    for (int q = 0; q < 4; q++)
        x4[q] = ((const float4*)xr)[lane * 4 + q];
    const float sqr = g_sq[r];

    // single pass: candidates -> exact recompute
    float ex = INF;
    const __half2* row2 = (const __half2*)row;
    for (int it = 0; it < 64; it++) {
        const int j2 = (it * 32 + lane) * 2;
        float2 f = __half22float2(row2[it * 32 + lane]);
        bool c0 = (f.x <= thresh) && (j2 != r) && (j2 != partner);
        bool c1 = (f.y <= thresh) && (j2 + 1 != r) && (j2 + 1 != partner);
        unsigned act = __ballot_sync(0xffffffffu, c0 || c1);
        unsigned pk = (c0 ? 1u : 0u) | (c1 ? 2u : 0u);
        while (act) {
            const int b = __ffs(act) - 1;
            act &= act - 1;
            const unsigned pb = __shfl_sync(0xffffffffu, pk, b);
            const int jb = __shfl_sync(0xffffffffu, j2, b);
            #pragma unroll
            for (int s = 0; s < 2; s++) {
                if (!(pb & (1u << s))) continue;
                const int j = jb + s;
                const float* yr = (j < NHALF) ? h1 + (size_t)j * DDIM
                                              : h2 + (size_t)(j - NHALF) * DDIM;
                float dot = 0.0f;
                #pragma unroll
                for (int q = 0; q < 4; q++) {
                    float4 yv = ((const float4*)yr)[lane * 4 + q];
                    dot += x4[q].x * yv.x + x4[q].y * yv.y
                         + x4[q].z * yv.z + x4[q].w * yv.w;
                }
                #pragma unroll
                for (int off = 16; off > 0; off >>= 1)
                    dot += __shfl_xor_sync(0xffffffffu, dot, off);
                ex = fminf(ex, clamp_dist(sqr + g_sq[j] - 2.0f * dot));
            }
        }
    }
    if (lane == 0) g_neg[r] = ex;

    // ---- fused finalize: last block to finish reduces everything ----
    __shared__ int s_last;
    __threadfence();
    __syncthreads();
    if (threadIdx.x == 0) {
        unsigned v = atomicAdd(&g_done, 1u);
        s_last = (v == RGRID - 1) ? 1 : 0;
    }
    __syncthreads();
    if (!s_last) return;

    const int t = threadIdx.x;
    float sumdiff = 0.0f, sumrel = 0.0f, sumsq = 0.0f;
    int nrel = 0, good = 0;
    #pragma unroll 4
    for (int i = t; i < NTOT; i += 256) {
        float diff = g_pos[i] - g_neg[i];
        float tl = fmaxf(diff + 0.1f, 0.0f);
        sumdiff += diff;
        if (tl > 1e-5f) { sumrel += tl; nrel++; }
        if (tl < 1e-5f) good++;
        sumsq += g_sq[i];
    }
    #pragma unroll
    for (int off = 16; off > 0; off >>= 1) {
        sumdiff += __shfl_xor_sync(0xffffffffu, sumdiff, off);
        sumrel  += __shfl_xor_sync(0xffffffffu, sumrel, off);
        sumsq   += __shfl_xor_sync(0xffffffffu, sumsq, off);
        nrel    += __shfl_xor_sync(0xffffffffu, nrel, off);
        good    += __shfl_xor_sync(0xffffffffu, good, off);
    }
    __shared__ float s_diff[8], s_rel[8], s_sq[8];
    __shared__ int   s_nrel[8], s_good[8];
    if (lane == 0) {
        s_diff[wid] = sumdiff; s_rel[wid] = sumrel; s_sq[wid] = sumsq;
        s_nrel[wid] = nrel;    s_good[wid] = good;
    }
    __syncthreads();
    if (t == 0) {
        float td = 0, tr = 0, tq = 0; int tn = 0, tg = 0;
        #pragma unroll
        for (int w = 0; w < 8; w++) {
            td += s_diff[w]; tr += s_rel[w]; tq += s_sq[w];
            tn += s_nrel[w]; tg += s_good[w];
        }
        int n_rel = tn > 0 ? tn : 1;
        out[0] = tr / (float)n_rel;
        out[1] = td / (float)NTOT;
        out[2] = (float)tg;
        out[3] = (float)(NTOT - tg);
        out[4] = sqrtf(tq / (float)NTOT);
    }
}

// ---------------------------------------------------------------------------
extern "C" void kernel_launch(void* const* d_in, const int* in_sizes, int n_in,
                              void* d_out, int out_size) {
    const float* h1 = (const float*)d_in[0];
    const float* h2 = (const float*)d_in[1];
    float* out = (float*)d_out;

    cudaFuncSetAttribute(gemm_dist_kernel,
                         cudaFuncAttributeMaxDynamicSharedMemorySize, SM_TOTAL);

    prep_kernel<<<NHALF / 8, 256>>>(h1, h2);
    gemm_dist_kernel<<<NBLK, 256, SM_TOTAL>>>();
    refine_kernel<<<RGRID, 256>>>(h1, h2, out);
}

// round 13
// speedup vs baseline: 1.0822x; 1.0822x over previous
#include <cuda_runtime.h>
#include <cuda_bf16.h>
#include <cuda_fp16.h>
#include <stdint.h>
#include <math.h>

#define NHALF 2048
#define NTOT  4096
#define DDIM  512

#define BM 128
#define BN 128
#define BK 32
#define NCHUNK (DDIM / BK)   // 16
#define NTILE 32
#define NBLK 528             // upper-triangle tiles

#define TPAD 40                      // bf16 per smem tile row (80 B)
#define TILE_B (128 * TPAD * 2)      // 10240 B
#define STAGE_B (2 * TILE_B)         // Ah, Bh only
#define SM_TOTAL (2 * STAGE_B)       // 40960 B (fp16 dist tile overlays)
#define DS_STRIDE 136                // halves per epilogue smem row

#define MARGIN 0.15f
#define RGRID 512                    // refine grid (8 rows per block)

// ---------------- device globals ----------------
__device__ float          g_sq[NTOT];
__device__ float          g_pos[NTOT];
__device__ float          g_neg[NTOT];
__device__ unsigned       g_done;
__device__ __nv_bfloat16  g_hi[NTOT * DDIM];
__device__ __half         g_dist[NTOT * NTOT];   // 32 MB approx dists

// ---------------- helpers ----------------
__device__ __forceinline__ uint32_t smem_u32(const void* p) {
    uint32_t a;
    asm("{ .reg .u64 t; cvta.to.shared.u64 t, %1; cvt.u32.u64 %0, t; }"
        : "=r"(a) : "l"(p));
    return a;
}
__device__ __forceinline__ void cp16(uint32_t dst, const void* src) {
    asm volatile("cp.async.cg.shared.global [%0], [%1], 16;"
                 :: "r"(dst), "l"(src));
}
#define CP_COMMIT() asm volatile("cp.async.commit_group;" ::: "memory")
#define CP_WAIT1()  asm volatile("cp.async.wait_group 1;" ::: "memory")
#define CP_WAIT0()  asm volatile("cp.async.wait_group 0;" ::: "memory")

__device__ __forceinline__ void ldx4(uint32_t* r, uint32_t addr) {
    asm volatile("ldmatrix.sync.aligned.m8n8.x4.shared.b16 {%0,%1,%2,%3}, [%4];"
                 : "=r"(r[0]), "=r"(r[1]), "=r"(r[2]), "=r"(r[3]) : "r"(addr));
}
__device__ __forceinline__ void mma16816(float* d, const uint32_t* a,
                                         const uint32_t* b) {
    asm volatile(
        "mma.sync.aligned.m16n8k16.row.col.f32.bf16.bf16.f32 "
        "{%0,%1,%2,%3}, {%4,%5,%6,%7}, {%8,%9}, {%0,%1,%2,%3};"
        : "+f"(d[0]), "+f"(d[1]), "+f"(d[2]), "+f"(d[3])
        : "r"(a[0]), "r"(a[1]), "r"(a[2]), "r"(a[3]), "r"(b[0]), "r"(b[1]));
}
__device__ __forceinline__ float clamp_dist(float d2) {
    return fmaxf(sqrtf(fmaxf(d2, 1e-14f)), 1e-7f);
}

// ---------------------------------------------------------------------------
// Kernel 1: per-pair sums of squares, exact positive dist, bf16-hi split,
//           done-counter reset
// ---------------------------------------------------------------------------
__global__ __launch_bounds__(256)
void prep_kernel(const float* __restrict__ h1,
                 const float* __restrict__ h2) {
    const int wid = threadIdx.x >> 5, lane = threadIdx.x & 31;
    const int r = blockIdx.x * 8 + wid;      // 0..2047
    const float* xr = h1 + (size_t)r * DDIM;
    const float* yr = h2 + (size_t)r * DDIM;

    float s1 = 0.0f, s2 = 0.0f, dt = 0.0f;
    #pragma unroll
    for (int u = 0; u < 4; u++) {
        const int fi = lane + 32 * u;
        float4 xv = ((const float4*)xr)[fi];
        float4 yv = ((const float4*)yr)[fi];
        s1 += xv.x * xv.x + xv.y * xv.y + xv.z * xv.z + xv.w * xv.w;
        s2 += yv.x * yv.x + yv.y * yv.y + yv.z * yv.z + yv.w * yv.w;
        dt += xv.x * yv.x + xv.y * yv.y + xv.z * yv.z + xv.w * yv.w;

        size_t bx = (size_t)r * DDIM + 4 * fi;
        __nv_bfloat162* gx = (__nv_bfloat162*)(g_hi + bx);
        gx[0] = __nv_bfloat162(__float2bfloat16(xv.x), __float2bfloat16(xv.y));
        gx[1] = __nv_bfloat162(__float2bfloat16(xv.z), __float2bfloat16(xv.w));
        __nv_bfloat162* gy = (__nv_bfloat162*)(g_hi + bx + (size_t)NHALF * DDIM);
        gy[0] = __nv_bfloat162(__float2bfloat16(yv.x), __float2bfloat16(yv.y));
        gy[1] = __nv_bfloat162(__float2bfloat16(yv.z), __float2bfloat16(yv.w));
    }

    #pragma unroll
    for (int off = 16; off > 0; off >>= 1) {
        s1 += __shfl_xor_sync(0xffffffffu, s1, off);
        s2 += __shfl_xor_sync(0xffffffffu, s2, off);
        dt += __shfl_xor_sync(0xffffffffu, dt, off);
    }

    if (lane == 0) {
        g_sq[r] = s1;
        g_sq[r + NHALF] = s2;
        float pos = clamp_dist(s1 + s2 - 2.0f * dt);
        g_pos[r] = pos;
        g_pos[r + NHALF] = pos;
        if (r == 0) g_done = 0u;
    }
}

// ---------------------------------------------------------------------------
// async-load one pipeline stage (2 tiles of 128 x 32 bf16: Ah, Bh)
// ---------------------------------------------------------------------------
__device__ __forceinline__ void load_stage(uint32_t smb, int stage,
                                           const __nv_bfloat16* ah,
                                           const __nv_bfloat16* bh,
                                           int k0, int tid) {
    const __nv_bfloat16* srcs[2] = {ah, bh};
    uint32_t base = smb + stage * STAGE_B;
    #pragma unroll
    for (int t = 0; t < 2; t++) {
        #pragma unroll
        for (int i = 0; i < 2; i++) {
            int chunk = tid * 2 + i;       // 0..511
            int r = chunk >> 2;            // 0..127
            int c = chunk & 3;             // 16B chunk within 64B row
            cp16(base + t * TILE_B + r * (TPAD * 2) + c * 16,
                 srcs[t] + (size_t)r * DDIM + k0 + c * 8);
        }
    }
}

// ---------------------------------------------------------------------------
// Kernel 2: hi-only bf16 mma.sync X*X^T (upper triangle); stores approx
// distances (fp16) for the tile and its transpose to g_dist
// ---------------------------------------------------------------------------
__global__ __launch_bounds__(256, 2)
void gemm_dist_kernel() {
    extern __shared__ char smem[];
    const uint32_t smb = smem_u32(smem);
    const int tid = threadIdx.x;
    const int wid = tid >> 5, lane = tid & 31;

    // decode upper-triangle tile index
    int t = blockIdx.x;
    int bi = 0;
    while (t >= NTILE - bi) { t -= NTILE - bi; bi++; }
    const int bj = bi + t;
    const int row0 = bi * BM;
    const int col0 = bj * BN;
    const bool isdiag = (bi == bj);

    const __nv_bfloat16* Ah_g = g_hi + (size_t)row0 * DDIM;
    const __nv_bfloat16* Bh_g = g_hi + (size_t)col0 * DDIM;

    // warp tile: 32 (M) x 64 (N)
    const int wm = wid & 3, wn = wid >> 2;
    const int m0 = wm * 32, n0 = wn * 64;

    float acc[2][8][4];
    #pragma unroll
    for (int i = 0; i < 2; i++)
        #pragma unroll
        for (int j = 0; j < 8; j++)
            #pragma unroll
            for (int q = 0; q < 4; q++)
                acc[i][j][q] = 0.0f;

    const int arow = (lane & 7) + ((lane >> 3) & 1) * 8;
    const int acol = (lane >> 4) * 8;
    const int brow = (lane & 7) + ((lane >> 4) << 3);
    const int bcol = ((lane >> 3) & 1) * 8;

    load_stage(smb, 0, Ah_g, Bh_g, 0, tid);
    CP_COMMIT();

    for (int it = 0; it < NCHUNK; it++) {
        if (it + 1 < NCHUNK) {
            load_stage(smb, (it + 1) & 1, Ah_g, Bh_g, (it + 1) * BK, tid);
            CP_COMMIT();
            CP_WAIT1();
        } else {
            CP_WAIT0();
        }
        __syncthreads();

        const uint32_t Ah = smb + (it & 1) * STAGE_B;
        const uint32_t Bh = Ah + TILE_B;

        #pragma unroll
        for (int ks = 0; ks < 2; ks++) {
            const int kb = ks * 16;
            uint32_t ahr[2][4];
            #pragma unroll
            for (int mt = 0; mt < 2; mt++) {
                uint32_t off = (uint32_t)(m0 + mt * 16 + arow) * (TPAD * 2)
                             + (kb + acol) * 2;
                ldx4(ahr[mt], Ah + off);
            }
            #pragma unroll
            for (int p = 0; p < 4; p++) {
                uint32_t off = (uint32_t)(n0 + p * 16 + brow) * (TPAD * 2)
                             + (kb + bcol) * 2;
                uint32_t rh[4];
                ldx4(rh, Bh + off);
                uint32_t b0h[2] = {rh[0], rh[1]}, b1h[2] = {rh[2], rh[3]};
                #pragma unroll
                for (int mt = 0; mt < 2; mt++) {
                    mma16816(acc[mt][2 * p],     ahr[mt], b0h);
                    mma16816(acc[mt][2 * p + 1], ahr[mt], b1h);
                }
            }
        }
        __syncthreads();
    }

    // ------------- epilogue: dist(fp16) into smem tile -------------
    __half* ds = (__half*)smem;
    const int g = lane >> 2;
    const int cl = (lane & 3) * 2;
    #pragma unroll
    for (int mt = 0; mt < 2; mt++) {
        const int rb = m0 + mt * 16 + g;
        #pragma unroll
        for (int nt = 0; nt < 8; nt++) {
            const int cb = n0 + nt * 8 + cl;
            #pragma unroll
            for (int h = 0; h < 2; h++) {
                const int rr = rb + h * 8;
                const float si = g_sq[row0 + rr];
                float d0 = clamp_dist(si + g_sq[col0 + cb]
                                      - 2.0f * acc[mt][nt][2 * h]);
                float d1 = clamp_dist(si + g_sq[col0 + cb + 1]
                                      - 2.0f * acc[mt][nt][2 * h + 1]);
                *(__half2*)&ds[rr * DS_STRIDE + cb] =
                    __floats2half2_rn(d0, d1);
            }
        }
    }
    __syncthreads();

    // row-orientation block: [row0..][col0..]
    {
        const int rb = tid >> 1, seg = tid & 1;
        const uint4* src = (const uint4*)&ds[rb * DS_STRIDE + seg * 64];
        uint4* dst = (uint4*)&g_dist[(size_t)(row0 + rb) * NTOT + col0 + seg * 64];
        #pragma unroll
        for (int q = 0; q < 8; q++) dst[q] = src[q];
    }
    // transposed block (off-diagonal only): [col0..][row0..]
    if (!isdiag) {
        const int c = tid >> 1, seg = tid & 1;
        __half v[64];
        #pragma unroll 8
        for (int k = 0; k < 64; k++)
            v[k] = ds[(seg * 64 + k) * DS_STRIDE + c];
        uint4* dst = (uint4*)&g_dist[(size_t)(col0 + c) * NTOT + row0 + seg * 64];
        const uint4* sv = (const uint4*)v;
        #pragma unroll
        for (int q = 0; q < 8; q++) dst[q] = sv[q];
    }
}

// ---------------------------------------------------------------------------
// Kernel 3: refine — approx min scan + exact recompute + fused finalize
// grid RGRID x 256 (8 warps); warp = one row
// ---------------------------------------------------------------------------
__global__ __launch_bounds__(256)
void refine_kernel(const float* __restrict__ h1,
                   const float* __restrict__ h2,
                   float* __restrict__ out) {
    const int wid = threadIdx.x >> 5, lane = threadIdx.x & 31;
    const int r = blockIdx.x * 8 + wid;          // 0..4095
    const int partner = r ^ NHALF;
    const float INF = __int_as_float(0x7f800000);

    const __half* row = g_dist + (size_t)r * NTOT;

    // pass 1: approximate min (excluding diag & partner)
    float mn = INF;
    const uint4* row4 = (const uint4*)row;
    #pragma unroll
    for (int it = 0; it < 16; it++) {
        const int idx = it * 32 + lane;          // uint4 index
        const int j0 = idx * 8;
        uint4 u = row4[idx];
        const __half2* hp = (const __half2*)&u;
        if (((unsigned)(r - j0) < 8u) || ((unsigned)(partner - j0) < 8u)) {
            #pragma unroll
            for (int h = 0; h < 4; h++) {
                float2 f = __half22float2(hp[h]);
                int j = j0 + 2 * h;
                if (j != r && j != partner) mn = fminf(mn, f.x);
                if (j + 1 != r && j + 1 != partner) mn = fminf(mn, f.y);
            }
        } else {
            #pragma unroll
            for (int h = 0; h < 4; h++) {
                float2 f = __half22float2(hp[h]);
                mn = fminf(mn, fminf(f.x, f.y));
            }
        }
    }
    #pragma unroll
    for (int off = 16; off > 0; off >>= 1)
        mn = fminf(mn, __shfl_xor_sync(0xffffffffu, mn, off));
    const float thresh = mn + MARGIN;

    // preload this row's fp32 data (16 dims per lane)
    const float* xr = (r < NHALF) ? h1 + (size_t)r * DDIM
                                  : h2 + (size_t)(r - NHALF) * DDIM;
    float4 x4[4];
    #pragma unroll
    for (int q = 0; q < 4; q++)
        x4[q] = ((const float4*)xr)[lane * 4 + q];
    const float sqr = g_sq[r];

    // pass 2: candidates -> exact recompute
    float ex = INF;
    const __half2* row2 = (const __half2*)row;
    for (int it = 0; it < 64; it++) {
        const int j2 = (it * 32 + lane) * 2;
        float2 f = __half22float2(row2[it * 32 + lane]);
        bool c0 = (f.x <= thresh) && (j2 != r) && (j2 != partner);
        bool c1 = (f.y <= thresh) && (j2 + 1 != r) && (j2 + 1 != partner);
        unsigned act = __ballot_sync(0xffffffffu, c0 || c1);
        unsigned pk = (c0 ? 1u : 0u) | (c1 ? 2u : 0u);
        while (act) {
            const int b = __ffs(act) - 1;
            act &= act - 1;
            const unsigned pb = __shfl_sync(0xffffffffu, pk, b);
            const int jb = __shfl_sync(0xffffffffu, j2, b);
            #pragma unroll
            for (int s = 0; s < 2; s++) {
                if (!(pb & (1u << s))) continue;
                const int j = jb + s;
                const float* yr = (j < NHALF) ? h1 + (size_t)j * DDIM
                                              : h2 + (size_t)(j - NHALF) * DDIM;
                float dot = 0.0f;
                #pragma unroll
                for (int q = 0; q < 4; q++) {
                    float4 yv = ((const float4*)yr)[lane * 4 + q];
                    dot += x4[q].x * yv.x + x4[q].y * yv.y
                         + x4[q].z * yv.z + x4[q].w * yv.w;
                }
                #pragma unroll
                for (int off = 16; off > 0; off >>= 1)
                    dot += __shfl_xor_sync(0xffffffffu, dot, off);
                ex = fminf(ex, clamp_dist(sqr + g_sq[j] - 2.0f * dot));
            }
        }
    }
    if (lane == 0) g_neg[r] = ex;

    // ---- fused finalize: last block to finish reduces everything ----
    __shared__ int s_last;
    __threadfence();
    __syncthreads();
    if (threadIdx.x == 0) {
        unsigned v = atomicAdd(&g_done, 1u);
        s_last = (v == RGRID - 1) ? 1 : 0;
    }
    __syncthreads();
    if (!s_last) return;

    const int t = threadIdx.x;
    float sumdiff = 0.0f, sumrel = 0.0f, sumsq = 0.0f;
    int nrel = 0, good = 0;
    #pragma unroll 4
    for (int i = t; i < NTOT; i += 256) {
        float diff = g_pos[i] - g_neg[i];
        float tl = fmaxf(diff + 0.1f, 0.0f);
        sumdiff += diff;
        if (tl > 1e-5f) { sumrel += tl; nrel++; }
        if (tl < 1e-5f) good++;
        sumsq += g_sq[i];
    }
    #pragma unroll
    for (int off = 16; off > 0; off >>= 1) {
        sumdiff += __shfl_xor_sync(0xffffffffu, sumdiff, off);
        sumrel  += __shfl_xor_sync(0xffffffffu, sumrel, off);
        sumsq   += __shfl_xor_sync(0xffffffffu, sumsq, off);
        nrel    += __shfl_xor_sync(0xffffffffu, nrel, off);
        good    += __shfl_xor_sync(0xffffffffu, good, off);
    }
    __shared__ float s_diff[8], s_rel[8], s_sq[8];
    __shared__ int   s_nrel[8], s_good[8];
    if (lane == 0) {
        s_diff[wid] = sumdiff; s_rel[wid] = sumrel; s_sq[wid] = sumsq;
        s_nrel[wid] = nrel;    s_good[wid] = good;
    }
    __syncthreads();
    if (t == 0) {
        float td = 0, tr = 0, tq = 0; int tn = 0, tg = 0;
        #pragma unroll
        for (int w = 0; w < 8; w++) {
            td += s_diff[w]; tr += s_rel[w]; tq += s_sq[w];
            tn += s_nrel[w]; tg += s_good[w];
        }
        int n_rel = tn > 0 ? tn : 1;
        out[0] = tr / (float)n_rel;
        out[1] = td / (float)NTOT;
        out[2] = (float)tg;
        out[3] = (float)(NTOT - tg);
        out[4] = sqrtf(tq / (float)NTOT);
    }
}

// ---------------------------------------------------------------------------
extern "C" void kernel_launch(void* const* d_in, const int* in_sizes, int n_in,
                              void* d_out, int out_size) {
    const float* h1 = (const float*)d_in[0];
    const float* h2 = (const float*)d_in[1];
    float* out = (float*)d_out;

    cudaFuncSetAttribute(gemm_dist_kernel,
                         cudaFuncAttributeMaxDynamicSharedMemorySize, SM_TOTAL);

    prep_kernel<<<NHALF / 8, 256>>>(h1, h2);
    gemm_dist_kernel<<<NBLK, 256, SM_TOTAL>>>();
    refine_kernel<<<RGRID, 256>>>(h1, h2, out);
}

// round 14
// speedup vs baseline: 1.1687x; 1.0799x over previous
#include <cuda_runtime.h>
#include <cuda_bf16.h>
#include <cuda_fp16.h>
#include <stdint.h>
#include <math.h>

#define NHALF 2048
#define NTOT  4096
#define DDIM  512

#define BM 128
#define BN 128
#define BK 32
#define NCHUNK (DDIM / BK)   // 16
#define NTILE 32
#define NBLK 528             // upper-triangle tiles

#define TPAD 40                      // bf16 per smem tile row (80 B)
#define TILE_B (128 * TPAD * 2)      // 10240 B
#define STAGE_B (2 * TILE_B)         // Ah, Bh per stage
#define NSTAGE 3
#define SM_TOTAL (NSTAGE * STAGE_B)  // 61440 B (fp16 dist tile overlays)
#define DS_STRIDE 136                // halves per epilogue smem row (34816 B)

#define MARGIN 0.15f
#define RGRID 512                    // refine grid (8 rows per block)

// ---------------- device globals ----------------
__device__ float          g_sq[NTOT];
__device__ float          g_pos[NTOT];
__device__ float          g_neg[NTOT];
__device__ unsigned       g_done;
__device__ __nv_bfloat16  g_hi[NTOT * DDIM];
__device__ __half         g_dist[NTOT * NTOT];   // 32 MB approx dists

// ---------------- helpers ----------------
__device__ __forceinline__ uint32_t smem_u32(const void* p) {
    uint32_t a;
    asm("{ .reg .u64 t; cvta.to.shared.u64 t, %1; cvt.u32.u64 %0, t; }"
        : "=r"(a) : "l"(p));
    return a;
}
__device__ __forceinline__ void cp16(uint32_t dst, const void* src) {
    asm volatile("cp.async.cg.shared.global [%0], [%1], 16;"
                 :: "r"(dst), "l"(src));
}
#define CP_COMMIT() asm volatile("cp.async.commit_group;" ::: "memory")
#define CP_WAIT2()  asm volatile("cp.async.wait_group 2;" ::: "memory")
#define CP_WAIT1()  asm volatile("cp.async.wait_group 1;" ::: "memory")
#define CP_WAIT0()  asm volatile("cp.async.wait_group 0;" ::: "memory")

__device__ __forceinline__ void ldx4(uint32_t* r, uint32_t addr) {
    asm volatile("ldmatrix.sync.aligned.m8n8.x4.shared.b16 {%0,%1,%2,%3}, [%4];"
                 : "=r"(r[0]), "=r"(r[1]), "=r"(r[2]), "=r"(r[3]) : "r"(addr));
}
__device__ __forceinline__ void mma16816(float* d, const uint32_t* a,
                                         const uint32_t* b) {
    asm volatile(
        "mma.sync.aligned.m16n8k16.row.col.f32.bf16.bf16.f32 "
        "{%0,%1,%2,%3}, {%4,%5,%6,%7}, {%8,%9}, {%0,%1,%2,%3};"
        : "+f"(d[0]), "+f"(d[1]), "+f"(d[2]), "+f"(d[3])
        : "r"(a[0]), "r"(a[1]), "r"(a[2]), "r"(a[3]), "r"(b[0]), "r"(b[1]));
}
__device__ __forceinline__ float clamp_dist(float d2) {
    return fmaxf(sqrtf(fmaxf(d2, 1e-14f)), 1e-7f);
}

// ---------------------------------------------------------------------------
// Kernel 1: per-pair sums of squares, exact positive dist, bf16-hi split,
//           done-counter reset
// ---------------------------------------------------------------------------
__global__ __launch_bounds__(256)
void prep_kernel(const float* __restrict__ h1,
                 const float* __restrict__ h2) {
    const int wid = threadIdx.x >> 5, lane = threadIdx.x & 31;
    const int r = blockIdx.x * 8 + wid;      // 0..2047
    const float* xr = h1 + (size_t)r * DDIM;
    const float* yr = h2 + (size_t)r * DDIM;

    float s1 = 0.0f, s2 = 0.0f, dt = 0.0f;
    #pragma unroll
    for (int u = 0; u < 4; u++) {
        const int fi = lane + 32 * u;
        float4 xv = ((const float4*)xr)[fi];
        float4 yv = ((const float4*)yr)[fi];
        s1 += xv.x * xv.x + xv.y * xv.y + xv.z * xv.z + xv.w * xv.w;
        s2 += yv.x * yv.x + yv.y * yv.y + yv.z * yv.z + yv.w * yv.w;
        dt += xv.x * yv.x + xv.y * yv.y + xv.z * yv.z + xv.w * yv.w;

        size_t bx = (size_t)r * DDIM + 4 * fi;
        __nv_bfloat162* gx = (__nv_bfloat162*)(g_hi + bx);
        gx[0] = __nv_bfloat162(__float2bfloat16(xv.x), __float2bfloat16(xv.y));
        gx[1] = __nv_bfloat162(__float2bfloat16(xv.z), __float2bfloat16(xv.w));
        __nv_bfloat162* gy = (__nv_bfloat162*)(g_hi + bx + (size_t)NHALF * DDIM);
        gy[0] = __nv_bfloat162(__float2bfloat16(yv.x), __float2bfloat16(yv.y));
        gy[1] = __nv_bfloat162(__float2bfloat16(yv.z), __float2bfloat16(yv.w));
    }

    #pragma unroll
    for (int off = 16; off > 0; off >>= 1) {
        s1 += __shfl_xor_sync(0xffffffffu, s1, off);
        s2 += __shfl_xor_sync(0xffffffffu, s2, off);
        dt += __shfl_xor_sync(0xffffffffu, dt, off);
    }

    if (lane == 0) {
        g_sq[r] = s1;
        g_sq[r + NHALF] = s2;
        float pos = clamp_dist(s1 + s2 - 2.0f * dt);
        g_pos[r] = pos;
        g_pos[r + NHALF] = pos;
        if (r == 0) g_done = 0u;
    }
}

// ---------------------------------------------------------------------------
// async-load one pipeline stage (2 tiles of 128 x 32 bf16: Ah, Bh)
// ---------------------------------------------------------------------------
__device__ __forceinline__ void load_stage(uint32_t smb, int stage,
                                           const __nv_bfloat16* ah,
                                           const __nv_bfloat16* bh,
                                           int k0, int tid) {
    const __nv_bfloat16* srcs[2] = {ah, bh};
    uint32_t base = smb + stage * STAGE_B;
    #pragma unroll
    for (int t = 0; t < 2; t++) {
        #pragma unroll
        for (int i = 0; i < 2; i++) {
            int chunk = tid * 2 + i;       // 0..511
            int r = chunk >> 2;            // 0..127
            int c = chunk & 3;             // 16B chunk within 64B row
            cp16(base + t * TILE_B + r * (TPAD * 2) + c * 16,
                 srcs[t] + (size_t)r * DDIM + k0 + c * 8);
        }
    }
}

// ---------------------------------------------------------------------------
// Kernel 2: hi-only bf16 mma.sync X*X^T (upper triangle), 3-stage pipeline;
// stores approx distances (fp16) for the tile and its transpose to g_dist
// ---------------------------------------------------------------------------
__global__ __launch_bounds__(256, 2)
void gemm_dist_kernel() {
    extern __shared__ char smem[];
    const uint32_t smb = smem_u32(smem);
    const int tid = threadIdx.x;
    const int wid = tid >> 5, lane = tid & 31;

    // decode upper-triangle tile index
    int t = blockIdx.x;
    int bi = 0;
    while (t >= NTILE - bi) { t -= NTILE - bi; bi++; }
    const int bj = bi + t;
    const int row0 = bi * BM;
    const int col0 = bj * BN;
    const bool isdiag = (bi == bj);

    const __nv_bfloat16* Ah_g = g_hi + (size_t)row0 * DDIM;
    const __nv_bfloat16* Bh_g = g_hi + (size_t)col0 * DDIM;

    // warp tile: 32 (M) x 64 (N)
    const int wm = wid & 3, wn = wid >> 2;
    const int m0 = wm * 32, n0 = wn * 64;

    float acc[2][8][4];
    #pragma unroll
    for (int i = 0; i < 2; i++)
        #pragma unroll
        for (int j = 0; j < 8; j++)
            #pragma unroll
            for (int q = 0; q < 4; q++)
                acc[i][j][q] = 0.0f;

    const int arow = (lane & 7) + ((lane >> 3) & 1) * 8;
    const int acol = (lane >> 4) * 8;
    const int brow = (lane & 7) + ((lane >> 4) << 3);
    const int bcol = ((lane >> 3) & 1) * 8;

    load_stage(smb, 0, Ah_g, Bh_g, 0, tid);
    CP_COMMIT();
    load_stage(smb, 1, Ah_g, Bh_g, BK, tid);
    CP_COMMIT();

    for (int it = 0; it < NCHUNK; it++) {
        if (it + 2 < NCHUNK) {
            load_stage(smb, (it + 2) % NSTAGE, Ah_g, Bh_g, (it + 2) * BK, tid);
            CP_COMMIT();
            CP_WAIT2();
        } else if (it + 1 < NCHUNK) {
            CP_WAIT1();
        } else {
            CP_WAIT0();
        }
        __syncthreads();

        const uint32_t Ah = smb + (it % NSTAGE) * STAGE_B;
        const uint32_t Bh = Ah + TILE_B;

        #pragma unroll
        for (int ks = 0; ks < 2; ks++) {
            const int kb = ks * 16;
            uint32_t ahr[2][4];
            #pragma unroll
            for (int mt = 0; mt < 2; mt++) {
                uint32_t off = (uint32_t)(m0 + mt * 16 + arow) * (TPAD * 2)
                             + (kb + acol) * 2;
                ldx4(ahr[mt], Ah + off);
            }
            #pragma unroll
            for (int p = 0; p < 4; p++) {
                uint32_t off = (uint32_t)(n0 + p * 16 + brow) * (TPAD * 2)
                             + (kb + bcol) * 2;
                uint32_t rh[4];
                ldx4(rh, Bh + off);
                uint32_t b0h[2] = {rh[0], rh[1]}, b1h[2] = {rh[2], rh[3]};
                #pragma unroll
                for (int mt = 0; mt < 2; mt++) {
                    mma16816(acc[mt][2 * p],     ahr[mt], b0h);
                    mma16816(acc[mt][2 * p + 1], ahr[mt], b1h);
                }
            }
        }
        __syncthreads();
    }

    // ------------- epilogue: dist(fp16) into smem tile -------------
    __half* ds = (__half*)smem;
    const int g = lane >> 2;
    const int cl = (lane & 3) * 2;
    #pragma unroll
    for (int mt = 0; mt < 2; mt++) {
        const int rb = m0 + mt * 16 + g;
        #pragma unroll
        for (int nt = 0; nt < 8; nt++) {
            const int cb = n0 + nt * 8 + cl;
            #pragma unroll
            for (int h = 0; h < 2; h++) {
                const int rr = rb + h * 8;
                const float si = g_sq[row0 + rr];
                float d0 = clamp_dist(si + g_sq[col0 + cb]
                                      - 2.0f * acc[mt][nt][2 * h]);
                float d1 = clamp_dist(si + g_sq[col0 + cb + 1]
                                      - 2.0f * acc[mt][nt][2 * h + 1]);
                *(__half2*)&ds[rr * DS_STRIDE + cb] =
                    __floats2half2_rn(d0, d1);
            }
        }
    }
    __syncthreads();

    // row-orientation block: [row0..][col0..]
    {
        const int rb = tid >> 1, seg = tid & 1;
        const uint4* src = (const uint4*)&ds[rb * DS_STRIDE + seg * 64];
        uint4* dst = (uint4*)&g_dist[(size_t)(row0 + rb) * NTOT + col0 + seg * 64];
        #pragma unroll
        for (int q = 0; q < 8; q++) dst[q] = src[q];
    }
    // transposed block (off-diagonal only): [col0..][row0..]
    if (!isdiag) {
        const int c = tid >> 1, seg = tid & 1;
        __half v[64];
        #pragma unroll 8
        for (int k = 0; k < 64; k++)
            v[k] = ds[(seg * 64 + k) * DS_STRIDE + c];
        uint4* dst = (uint4*)&g_dist[(size_t)(col0 + c) * NTOT + row0 + seg * 64];
        const uint4* sv = (const uint4*)v;
        #pragma unroll
        for (int q = 0; q < 8; q++) dst[q] = sv[q];
    }
}

// ---------------------------------------------------------------------------
// Kernel 3: refine — hmin2 approx-min scan + exact recompute + fused finalize
// grid RGRID x 256 (8 warps); warp = one row
// ---------------------------------------------------------------------------
__global__ __launch_bounds__(256)
void refine_kernel(const float* __restrict__ h1,
                   const float* __restrict__ h2,
                   float* __restrict__ out) {
    const int wid = threadIdx.x >> 5, lane = threadIdx.x & 31;
    const int r = blockIdx.x * 8 + wid;          // 0..4095
    const int partner = r ^ NHALF;
    const float INF = __int_as_float(0x7f800000);

    const __half* row = g_dist + (size_t)r * NTOT;

    // pass 1: approximate min via native half2 mins
    const __half2 H2MAX = __halves2half2(__ushort_as_half(0x7bffu),
                                         __ushort_as_half(0x7bffu));
    __half2 m2 = H2MAX;
    float mn_excl = INF;   // mins from exclusion-containing blocks
    const uint4* row4 = (const uint4*)row;
    #pragma unroll
    for (int it = 0; it < 16; it++) {
        const int idx = it * 32 + lane;          // uint4 index
        const int j0 = idx * 8;
        uint4 u = row4[idx];
        const __half2* hp = (const __half2*)&u;
        if (((unsigned)(r - j0) < 8u) || ((unsigned)(partner - j0) < 8u)) {
            #pragma unroll
            for (int h = 0; h < 4; h++) {
                float2 f = __half22float2(hp[h]);
                int j = j0 + 2 * h;
                if (j != r && j != partner) mn_excl = fminf(mn_excl, f.x);
                if (j + 1 != r && j + 1 != partner) mn_excl = fminf(mn_excl, f.y);
            }
        } else {
            m2 = __hmin2(m2, __hmin2(__hmin2(hp[0], hp[1]),
                                     __hmin2(hp[2], hp[3])));
        }
    }
    float mn = fminf(mn_excl,
                     fminf(__low2float(m2), __high2float(m2)));
    #pragma unroll
    for (int off = 16; off > 0; off >>= 1)
        mn = fminf(mn, __shfl_xor_sync(0xffffffffu, mn, off));
    const float thresh = mn + MARGIN;

    // preload this row's fp32 data (16 dims per lane)
    const float* xr = (r < NHALF) ? h1 + (size_t)r * DDIM
                                  : h2 + (size_t)(r - NHALF) * DDIM;
    float4 x4[4];
    #pragma unroll
    for (int q = 0; q < 4; q++)
        x4[q] = ((const float4*)xr)[lane * 4 + q];
    const float sqr = g_sq[r];

    // pass 2: candidates -> exact recompute
    float ex = INF;
    const __half2* row2 = (const __half2*)row;
    for (int it = 0; it < 64; it++) {
        const int j2 = (it * 32 + lane) * 2;
        float2 f = __half22float2(row2[it * 32 + lane]);
        bool c0 = (f.x <= thresh) && (j2 != r) && (j2 != partner);
        bool c1 = (f.y <= thresh) && (j2 + 1 != r) && (j2 + 1 != partner);
        unsigned act = __ballot_sync(0xffffffffu, c0 || c1);
        unsigned pk = (c0 ? 1u : 0u) | (c1 ? 2u : 0u);
        while (act) {
            const int b = __ffs(act) - 1;
            act &= act - 1;
            const unsigned pb = __shfl_sync(0xffffffffu, pk, b);
            const int jb = __shfl_sync(0xffffffffu, j2, b);
            #pragma unroll
            for (int s = 0; s < 2; s++) {
                if (!(pb & (1u << s))) continue;
                const int j = jb + s;
                const float* yr = (j < NHALF) ? h1 + (size_t)j * DDIM
                                              : h2 + (size_t)(j - NHALF) * DDIM;
                float dot = 0.0f;
                #pragma unroll
                for (int q = 0; q < 4; q++) {
                    float4 yv = ((const float4*)yr)[lane * 4 + q];
                    dot += x4[q].x * yv.x + x4[q].y * yv.y
                         + x4[q].z * yv.z + x4[q].w * yv.w;
                }
                #pragma unroll
                for (int off = 16; off > 0; off >>= 1)
                    dot += __shfl_xor_sync(0xffffffffu, dot, off);
                ex = fminf(ex, clamp_dist(sqr + g_sq[j] - 2.0f * dot));
            }
        }
    }
    if (lane == 0) g_neg[r] = ex;

    // ---- fused finalize: last block to finish reduces everything ----
    __shared__ int s_last;
    __threadfence();
    __syncthreads();
    if (threadIdx.x == 0) {
        unsigned v = atomicAdd(&g_done, 1u);
        s_last = (v == RGRID - 1) ? 1 : 0;
    }
    __syncthreads();
    if (!s_last) return;

    const int t = threadIdx.x;
    float sumdiff = 0.0f, sumrel = 0.0f, sumsq = 0.0f;
    int nrel = 0, good = 0;
    #pragma unroll 4
    for (int i = t; i < NTOT; i += 256) {
        float diff = g_pos[i] - g_neg[i];
        float tl = fmaxf(diff + 0.1f, 0.0f);
        sumdiff += diff;
        if (tl > 1e-5f) { sumrel += tl; nrel++; }
        if (tl < 1e-5f) good++;
        sumsq += g_sq[i];
    }
    #pragma unroll
    for (int off = 16; off > 0; off >>= 1) {
        sumdiff += __shfl_xor_sync(0xffffffffu, sumdiff, off);
        sumrel  += __shfl_xor_sync(0xffffffffu, sumrel, off);
        sumsq   += __shfl_xor_sync(0xffffffffu, sumsq, off);
        nrel    += __shfl_xor_sync(0xffffffffu, nrel, off);
        good    += __shfl_xor_sync(0xffffffffu, good, off);
    }
    __shared__ float s_diff[8], s_rel[8], s_sq[8];
    __shared__ int   s_nrel[8], s_good[8];
    if (lane == 0) {
        s_diff[wid] = sumdiff; s_rel[wid] = sumrel; s_sq[wid] = sumsq;
        s_nrel[wid] = nrel;    s_good[wid] = good;
    }
    __syncthreads();
    if (t == 0) {
        float td = 0, tr = 0, tq = 0; int tn = 0, tg = 0;
        #pragma unroll
        for (int w = 0; w < 8; w++) {
            td += s_diff[w]; tr += s_rel[w]; tq += s_sq[w];
            tn += s_nrel[w]; tg += s_good[w];
        }
        int n_rel = tn > 0 ? tn : 1;
        out[0] = tr / (float)n_rel;
        out[1] = td / (float)NTOT;
        out[2] = (float)tg;
        out[3] = (float)(NTOT - tg);
        out[4] = sqrtf(tq / (float)NTOT);
    }
}

// ---------------------------------------------------------------------------
extern "C" void kernel_launch(void* const* d_in, const int* in_sizes, int n_in,
                              void* d_out, int out_size) {
    const float* h1 = (const float*)d_in[0];
    const float* h2 = (const float*)d_in[1];
    float* out = (float*)d_out;

    cudaFuncSetAttribute(gemm_dist_kernel,
                         cudaFuncAttributeMaxDynamicSharedMemorySize, SM_TOTAL);

    prep_kernel<<<NHALF / 8, 256>>>(h1, h2);
    gemm_dist_kernel<<<NBLK, 256, SM_TOTAL>>>();
    refine_kernel<<<RGRID, 256>>>(h1, h2, out);
}

// round 15
// speedup vs baseline: 1.3251x; 1.1338x over previous
#include <cuda_runtime.h>
#include <cuda_bf16.h>
#include <cuda_fp16.h>
#include <stdint.h>
#include <math.h>

#define NHALF 2048
#define NTOT  4096
#define DDIM  512

#define BM 128
#define BN 128
#define BK 32
#define NCHUNK (DDIM / BK)   // 16
#define NTILE 32
#define NBLK 528             // upper-triangle tiles

#define TPAD 40                      // bf16 per smem tile row (80 B)
#define TILE_B (128 * TPAD * 2)      // 10240 B
#define STAGE_B (2 * TILE_B)         // Ah, Bh per stage
#define NSTAGE 3
#define SM_TOTAL (NSTAGE * STAGE_B)  // 61440 B
#define DS_STRIDE 136                // halves per epilogue smem row
#define SM_MIN (128 * DS_STRIDE * 2) // 34816: row/col min arrays after tile

#define MARGIN 0.15f
#define RGRID 512                    // refine grid (8 rows per block)

// ---------------- device globals ----------------
__device__ float          g_sq[NTOT];
__device__ float          g_pos[NTOT];
__device__ float          g_neg[NTOT];
__device__ unsigned       g_negmin_bits[NTOT];  // approx min d^2 (float bits)
__device__ unsigned       g_done;
__device__ __nv_bfloat16  g_hi[NTOT * DDIM];
__device__ __half         g_dist[NTOT * NTOT];  // 32 MB approx dists

// ---------------- helpers ----------------
__device__ __forceinline__ uint32_t smem_u32(const void* p) {
    uint32_t a;
    asm("{ .reg .u64 t; cvta.to.shared.u64 t, %1; cvt.u32.u64 %0, t; }"
        : "=r"(a) : "l"(p));
    return a;
}
__device__ __forceinline__ void cp16(uint32_t dst, const void* src) {
    asm volatile("cp.async.cg.shared.global [%0], [%1], 16;"
                 :: "r"(dst), "l"(src));
}
#define CP_COMMIT() asm volatile("cp.async.commit_group;" ::: "memory")
#define CP_WAIT2()  asm volatile("cp.async.wait_group 2;" ::: "memory")
#define CP_WAIT1()  asm volatile("cp.async.wait_group 1;" ::: "memory")
#define CP_WAIT0()  asm volatile("cp.async.wait_group 0;" ::: "memory")

__device__ __forceinline__ void ldx4(uint32_t* r, uint32_t addr) {
    asm volatile("ldmatrix.sync.aligned.m8n8.x4.shared.b16 {%0,%1,%2,%3}, [%4];"
                 : "=r"(r[0]), "=r"(r[1]), "=r"(r[2]), "=r"(r[3]) : "r"(addr));
}
__device__ __forceinline__ void mma16816(float* d, const uint32_t* a,
                                         const uint32_t* b) {
    asm volatile(
        "mma.sync.aligned.m16n8k16.row.col.f32.bf16.bf16.f32 "
        "{%0,%1,%2,%3}, {%4,%5,%6,%7}, {%8,%9}, {%0,%1,%2,%3};"
        : "+f"(d[0]), "+f"(d[1]), "+f"(d[2]), "+f"(d[3])
        : "r"(a[0]), "r"(a[1]), "r"(a[2]), "r"(a[3]), "r"(b[0]), "r"(b[1]));
}
__device__ __forceinline__ float clamp_dist(float d2) {
    return fmaxf(sqrtf(fmaxf(d2, 1e-14f)), 1e-7f);
}

// ---------------------------------------------------------------------------
// Kernel 1: per-pair sums of squares, exact positive dist, bf16-hi split,
//           negmin + done-counter reset
// ---------------------------------------------------------------------------
__global__ __launch_bounds__(256)
void prep_kernel(const float* __restrict__ h1,
                 const float* __restrict__ h2) {
    const int wid = threadIdx.x >> 5, lane = threadIdx.x & 31;
    const int r = blockIdx.x * 8 + wid;      // 0..2047
    const float* xr = h1 + (size_t)r * DDIM;
    const float* yr = h2 + (size_t)r * DDIM;

    float s1 = 0.0f, s2 = 0.0f, dt = 0.0f;
    #pragma unroll
    for (int u = 0; u < 4; u++) {
        const int fi = lane + 32 * u;
        float4 xv = ((const float4*)xr)[fi];
        float4 yv = ((const float4*)yr)[fi];
        s1 += xv.x * xv.x + xv.y * xv.y + xv.z * xv.z + xv.w * xv.w;
        s2 += yv.x * yv.x + yv.y * yv.y + yv.z * yv.z + yv.w * yv.w;
        dt += xv.x * yv.x + xv.y * yv.y + xv.z * yv.z + xv.w * yv.w;

        size_t bx = (size_t)r * DDIM + 4 * fi;
        __nv_bfloat162* gx = (__nv_bfloat162*)(g_hi + bx);
        gx[0] = __nv_bfloat162(__float2bfloat16(xv.x), __float2bfloat16(xv.y));
        gx[1] = __nv_bfloat162(__float2bfloat16(xv.z), __float2bfloat16(xv.w));
        __nv_bfloat162* gy = (__nv_bfloat162*)(g_hi + bx + (size_t)NHALF * DDIM);
        gy[0] = __nv_bfloat162(__float2bfloat16(yv.x), __float2bfloat16(yv.y));
        gy[1] = __nv_bfloat162(__float2bfloat16(yv.z), __float2bfloat16(yv.w));
    }

    #pragma unroll
    for (int off = 16; off > 0; off >>= 1) {
        s1 += __shfl_xor_sync(0xffffffffu, s1, off);
        s2 += __shfl_xor_sync(0xffffffffu, s2, off);
        dt += __shfl_xor_sync(0xffffffffu, dt, off);
    }

    if (lane == 0) {
        g_sq[r] = s1;
        g_sq[r + NHALF] = s2;
        float pos = clamp_dist(s1 + s2 - 2.0f * dt);
        g_pos[r] = pos;
        g_pos[r + NHALF] = pos;
        g_negmin_bits[r] = 0x7f800000u;
        g_negmin_bits[r + NHALF] = 0x7f800000u;
        if (r == 0) g_done = 0u;
    }
}

// ---------------------------------------------------------------------------
// async-load one pipeline stage (2 tiles of 128 x 32 bf16: Ah, Bh)
// ---------------------------------------------------------------------------
__device__ __forceinline__ void load_stage(uint32_t smb, int stage,
                                           const __nv_bfloat16* ah,
                                           const __nv_bfloat16* bh,
                                           int k0, int tid) {
    const __nv_bfloat16* srcs[2] = {ah, bh};
    uint32_t base = smb + stage * STAGE_B;
    #pragma unroll
    for (int t = 0; t < 2; t++) {
        #pragma unroll
        for (int i = 0; i < 2; i++) {
            int chunk = tid * 2 + i;       // 0..511
            int r = chunk >> 2;            // 0..127
            int c = chunk & 3;             // 16B chunk within 64B row
            cp16(base + t * TILE_B + r * (TPAD * 2) + c * 16,
                 srcs[t] + (size_t)r * DDIM + k0 + c * 8);
        }
    }
}

// ---------------------------------------------------------------------------
// Kernel 2: hi-only bf16 mma.sync X*X^T (upper triangle), 3-stage pipeline;
// stores approx dists (fp16) both orientations + register-space d^2 minima
// ---------------------------------------------------------------------------
__global__ __launch_bounds__(256, 2)
void gemm_dist_kernel() {
    extern __shared__ char smem[];
    const uint32_t smb = smem_u32(smem);
    const int tid = threadIdx.x;
    const int wid = tid >> 5, lane = tid & 31;

    // decode upper-triangle tile index
    int t = blockIdx.x;
    int bi = 0;
    while (t >= NTILE - bi) { t -= NTILE - bi; bi++; }
    const int bj = bi + t;
    const int row0 = bi * BM;
    const int col0 = bj * BN;
    const bool isdiag = (bi == bj);

    const __nv_bfloat16* Ah_g = g_hi + (size_t)row0 * DDIM;
    const __nv_bfloat16* Bh_g = g_hi + (size_t)col0 * DDIM;

    // warp tile: 32 (M) x 64 (N)
    const int wm = wid & 3, wn = wid >> 2;
    const int m0 = wm * 32, n0 = wn * 64;

    float acc[2][8][4];
    #pragma unroll
    for (int i = 0; i < 2; i++)
        #pragma unroll
        for (int j = 0; j < 8; j++)
            #pragma unroll
            for (int q = 0; q < 4; q++)
                acc[i][j][q] = 0.0f;

    const int arow = (lane & 7) + ((lane >> 3) & 1) * 8;
    const int acol = (lane >> 4) * 8;
    const int brow = (lane & 7) + ((lane >> 4) << 3);
    const int bcol = ((lane >> 3) & 1) * 8;

    load_stage(smb, 0, Ah_g, Bh_g, 0, tid);
    CP_COMMIT();
    load_stage(smb, 1, Ah_g, Bh_g, BK, tid);
    CP_COMMIT();

    for (int it = 0; it < NCHUNK; it++) {
        if (it + 2 < NCHUNK) {
            load_stage(smb, (it + 2) % NSTAGE, Ah_g, Bh_g, (it + 2) * BK, tid);
            CP_COMMIT();
            CP_WAIT2();
        } else if (it + 1 < NCHUNK) {
            CP_WAIT1();
        } else {
            CP_WAIT0();
        }
        __syncthreads();

        const uint32_t Ah = smb + (it % NSTAGE) * STAGE_B;
        const uint32_t Bh = Ah + TILE_B;

        #pragma unroll
        for (int ks = 0; ks < 2; ks++) {
            const int kb = ks * 16;
            uint32_t ahr[2][4];
            #pragma unroll
            for (int mt = 0; mt < 2; mt++) {
                uint32_t off = (uint32_t)(m0 + mt * 16 + arow) * (TPAD * 2)
                             + (kb + acol) * 2;
                ldx4(ahr[mt], Ah + off);
            }
            #pragma unroll
            for (int p = 0; p < 4; p++) {
                uint32_t off = (uint32_t)(n0 + p * 16 + brow) * (TPAD * 2)
                             + (kb + bcol) * 2;
                uint32_t rh[4];
                ldx4(rh, Bh + off);
                uint32_t b0h[2] = {rh[0], rh[1]}, b1h[2] = {rh[2], rh[3]};
                #pragma unroll
                for (int mt = 0; mt < 2; mt++) {
                    mma16816(acc[mt][2 * p],     ahr[mt], b0h);
                    mma16816(acc[mt][2 * p + 1], ahr[mt], b1h);
                }
            }
        }
        __syncthreads();
    }

    // ---------------- epilogue ----------------
    const float INF = __int_as_float(0x7f800000);
    const int g = lane >> 2;
    const int cl = (lane & 3) * 2;

    // hoisted norms
    float si[4], sqj[16];
    #pragma unroll
    for (int s = 0; s < 4; s++)
        si[s] = g_sq[row0 + m0 + (s >> 1) * 16 + (s & 1) * 8 + g];
    #pragma unroll
    for (int nt = 0; nt < 8; nt++) {
        sqj[2 * nt]     = g_sq[col0 + n0 + nt * 8 + cl];
        sqj[2 * nt + 1] = g_sq[col0 + n0 + nt * 8 + cl + 1];
    }

    // register-space d^2 + row/col mins + fp16 tile write
    __half* ds = (__half*)smem;
    unsigned* s_rmin = (unsigned*)(smem + SM_MIN);
    unsigned* s_cmin = (unsigned*)(smem + SM_MIN + 512);
    ((unsigned*)(smem + SM_MIN))[tid] = 0x7f800000u;  // init both arrays

    float rowv[4], colv[16];
    #pragma unroll
    for (int s = 0; s < 4; s++) rowv[s] = INF;
    #pragma unroll
    for (int s = 0; s < 16; s++) colv[s] = INF;

    #pragma unroll
    for (int mt = 0; mt < 2; mt++) {
        #pragma unroll
        for (int nt = 0; nt < 8; nt++) {
            float dv[4];
            #pragma unroll
            for (int q = 0; q < 4; q++) {
                const int rs = mt * 2 + (q >> 1);
                const int cs = nt * 2 + (q & 1);
                const int gi = row0 + m0 + mt * 16 + (q >> 1) * 8 + g;
                const int gj = col0 + n0 + nt * 8 + cl + (q & 1);
                float d2 = si[rs] + sqj[cs] - 2.0f * acc[mt][nt][q];
                dv[q] = d2;
                bool excl = (gj == gi) || (gj == (gi ^ NHALF));
                float v = excl ? INF : fmaxf(d2, 0.0f);
                rowv[rs] = fminf(rowv[rs], v);
                colv[cs] = fminf(colv[cs], v);
            }
            // fp16 dist tile entries
            const int rb = m0 + mt * 16 + g;
            const int cb = n0 + nt * 8 + cl;
            *(__half2*)&ds[rb * DS_STRIDE + cb] = __floats2half2_rn(
                clamp_dist(dv[0]), clamp_dist(dv[1]));
            *(__half2*)&ds[(rb + 8) * DS_STRIDE + cb] = __floats2half2_rn(
                clamp_dist(dv[2]), clamp_dist(dv[3]));
        }
    }

    // reduce rows over cl (xor 1,2), cols over g (xor 4,8,16)
    #pragma unroll
    for (int off = 1; off <= 2; off <<= 1)
        #pragma unroll
        for (int s = 0; s < 4; s++)
            rowv[s] = fminf(rowv[s], __shfl_xor_sync(0xffffffffu, rowv[s], off));
    #pragma unroll
    for (int off = 4; off <= 16; off <<= 1)
        #pragma unroll
        for (int s = 0; s < 16; s++)
            colv[s] = fminf(colv[s], __shfl_xor_sync(0xffffffffu, colv[s], off));

    __syncthreads();
    if ((lane & 3) == 0) {
        #pragma unroll
        for (int s = 0; s < 4; s++)
            atomicMin(&s_rmin[m0 + (s >> 1) * 16 + (s & 1) * 8 + g],
                      __float_as_uint(rowv[s]));
    }
    if (lane < 4) {
        #pragma unroll
        for (int s = 0; s < 16; s++)
            atomicMin(&s_cmin[n0 + (s >> 1) * 8 + cl + (s & 1)],
                      __float_as_uint(colv[s]));
    }
    __syncthreads();

    // global stores: row block + approx-min atomics
    {
        const int rb = tid >> 1, seg = tid & 1;
        const uint4* src = (const uint4*)&ds[rb * DS_STRIDE + seg * 64];
        uint4* dst = (uint4*)&g_dist[(size_t)(row0 + rb) * NTOT + col0 + seg * 64];
        #pragma unroll
        for (int q = 0; q < 8; q++) dst[q] = src[q];
    }
    if (!isdiag) {
        const int c = tid >> 1, seg = tid & 1;
        __half v[64];
        #pragma unroll 8
        for (int k = 0; k < 64; k++)
            v[k] = ds[(seg * 64 + k) * DS_STRIDE + c];
        uint4* dst = (uint4*)&g_dist[(size_t)(col0 + c) * NTOT + row0 + seg * 64];
        const uint4* sv = (const uint4*)v;
        #pragma unroll
        for (int q = 0; q < 8; q++) dst[q] = sv[q];
    }
    if (tid < 128) {
        atomicMin(&g_negmin_bits[row0 + tid], s_rmin[tid]);
    } else if (!isdiag) {
        atomicMin(&g_negmin_bits[col0 + tid - 128], s_cmin[tid - 128]);
    }
}

// ---------------------------------------------------------------------------
// Kernel 3: refine — single vectorized candidate pass + exact recompute
//           + fused finalize.  grid RGRID x 256 (8 warps); warp = one row
// ---------------------------------------------------------------------------
__global__ __launch_bounds__(256)
void refine_kernel(const float* __restrict__ h1,
                   const float* __restrict__ h2,
                   float* __restrict__ out) {
    const int wid = threadIdx.x >> 5, lane = threadIdx.x & 31;
    const int r = blockIdx.x * 8 + wid;          // 0..4095
    const int partner = r ^ NHALF;
    const float INF = __int_as_float(0x7f800000);

    const float d2min = fmaxf(__uint_as_float(g_negmin_bits[r]), 0.0f);
    const float thresh = sqrtf(d2min) + MARGIN;
    const __half hthresh = __float2half_rn(thresh + 0.01f);

    const __half* row = g_dist + (size_t)r * NTOT;
    const uint4* row4 = (const uint4*)row;

    // preload this row's fp32 data (16 dims per lane)
    const float* xr = (r < NHALF) ? h1 + (size_t)r * DDIM
                                  : h2 + (size_t)(r - NHALF) * DDIM;
    float4 x4[4];
    #pragma unroll
    for (int q = 0; q < 4; q++)
        x4[q] = ((const float4*)xr)[lane * 4 + q];
    const float sqr = g_sq[r];

    float ex = INF;
    #pragma unroll 4
    for (int it = 0; it < 16; it++) {
        const int idx = it * 32 + lane;          // uint4 index
        const int j0 = idx * 8;
        uint4 u = row4[idx];
        const __half2* hp = (const __half2*)&u;

        __half2 mm = __hmin2(__hmin2(hp[0], hp[1]), __hmin2(hp[2], hp[3]));
        __half m = __hmin(__low2half(mm), __high2half(mm));
        unsigned cmask = 0;
        if (__hle(m, hthresh)) {
            #pragma unroll
            for (int h = 0; h < 4; h++) {
                float2 f = __half22float2(hp[h]);
                const int j = j0 + 2 * h;
                if (f.x <= thresh && j != r && j != partner)
                    cmask |= 1u << (2 * h);
                if (f.y <= thresh && j + 1 != r && j + 1 != partner)
                    cmask |= 1u << (2 * h + 1);
            }
        }
        unsigned act = __ballot_sync(0xffffffffu, cmask != 0);
        while (act) {
            const int b = __ffs(act) - 1;
            act &= act - 1;
            unsigned pb = __shfl_sync(0xffffffffu, cmask, b);
            const int jb = __shfl_sync(0xffffffffu, j0, b);
            while (pb) {
                const int s = __ffs(pb) - 1;
                pb &= pb - 1;
                const int j = jb + s;
                const float* yr = (j < NHALF) ? h1 + (size_t)j * DDIM
                                              : h2 + (size_t)(j - NHALF) * DDIM;
                float dot = 0.0f;
                #pragma unroll
                for (int q = 0; q < 4; q++) {
                    float4 yv = ((const float4*)yr)[lane * 4 + q];
                    dot += x4[q].x * yv.x + x4[q].y * yv.y
                         + x4[q].z * yv.z + x4[q].w * yv.w;
                }
                #pragma unroll
                for (int off = 16; off > 0; off >>= 1)
                    dot += __shfl_xor_sync(0xffffffffu, dot, off);
                ex = fminf(ex, clamp_dist(sqr + g_sq[j] - 2.0f * dot));
            }
        }
    }
    if (lane == 0) g_neg[r] = ex;

    // ---- fused finalize: last block to finish reduces everything ----
    __shared__ int s_last;
    __threadfence();
    __syncthreads();
    if (threadIdx.x == 0) {
        unsigned v = atomicAdd(&g_done, 1u);
        s_last = (v == RGRID - 1) ? 1 : 0;
    }
    __syncthreads();
    if (!s_last) return;

    const int t = threadIdx.x;
    float sumdiff = 0.0f, sumrel = 0.0f, sumsq = 0.0f;
    int nrel = 0, good = 0;
    #pragma unroll 4
    for (int i = t; i < NTOT; i += 256) {
        float diff = g_pos[i] - g_neg[i];
        float tl = fmaxf(diff + 0.1f, 0.0f);
        sumdiff += diff;
        if (tl > 1e-5f) { sumrel += tl; nrel++; }
        if (tl < 1e-5f) good++;
        sumsq += g_sq[i];
    }
    #pragma unroll
    for (int off = 16; off > 0; off >>= 1) {
        sumdiff += __shfl_xor_sync(0xffffffffu, sumdiff, off);
        sumrel  += __shfl_xor_sync(0xffffffffu, sumrel, off);
        sumsq   += __shfl_xor_sync(0xffffffffu, sumsq, off);
        nrel    += __shfl_xor_sync(0xffffffffu, nrel, off);
        good    += __shfl_xor_sync(0xffffffffu, good, off);
    }
    __shared__ float s_diff[8], s_rel[8], s_sq[8];
    __shared__ int   s_nrel[8], s_good[8];
    if (lane == 0) {
        s_diff[wid] = sumdiff; s_rel[wid] = sumrel; s_sq[wid] = sumsq;
        s_nrel[wid] = nrel;    s_good[wid] = good;
    }
    __syncthreads();
    if (t == 0) {
        float td = 0, tr = 0, tq = 0; int tn = 0, tg = 0;
        #pragma unroll
        for (int w = 0; w < 8; w++) {
            td += s_diff[w]; tr += s_rel[w]; tq += s_sq[w];
            tn += s_nrel[w]; tg += s_good[w];
        }
        int n_rel = tn > 0 ? tn : 1;
        out[0] = tr / (float)n_rel;
        out[1] = td / (float)NTOT;
        out[2] = (float)tg;
        out[3] = (float)(NTOT - tg);
        out[4] = sqrtf(tq / (float)NTOT);
    }
}

// ---------------------------------------------------------------------------
extern "C" void kernel_launch(void* const* d_in, const int* in_sizes, int n_in,
                              void* d_out, int out_size) {
    const float* h1 = (const float*)d_in[0];
    const float* h2 = (const float*)d_in[1];
    float* out = (float*)d_out;

    cudaFuncSetAttribute(gemm_dist_kernel,
                         cudaFuncAttributeMaxDynamicSharedMemorySize, SM_TOTAL);

    prep_kernel<<<NHALF / 8, 256>>>(h1, h2);
    gemm_dist_kernel<<<NBLK, 256, SM_TOTAL>>>();
    refine_kernel<<<RGRID, 256>>>(h1, h2, out);
}

// round 16
// speedup vs baseline: 1.3575x; 1.0245x over previous
#include <cuda_runtime.h>
#include <cuda_bf16.h>
#include <cuda_fp16.h>
#include <stdint.h>
#include <math.h>

#define NHALF 2048
#define NTOT  4096
#define DDIM  512

#define BM 128
#define BN 128
#define BK 32
#define NCHUNK (DDIM / BK)   // 16
#define NTILE 32
#define NBLK 528             // upper-triangle tiles

#define TPAD 40                      // bf16 per smem tile row (80 B)
#define TILE_B (128 * TPAD * 2)      // 10240 B
#define STAGE_B (2 * TILE_B)         // Ah, Bh per stage
#define NSTAGE 3
#define SM_TOTAL (NSTAGE * STAGE_B)  // 61440 B
#define DS_STRIDE 136                // halves per epilogue smem row
#define SM_MIN (128 * DS_STRIDE * 2) // 34816: row/col min arrays after tile

#define MARGIN 0.15f
#define RGRID 512                    // refine grid (8 rows per block)

// ---------------- device globals ----------------
__device__ float          g_sq[NTOT];
__device__ float          g_pos[NTOT];
__device__ float          g_neg[NTOT];
__device__ unsigned       g_negmin_bits[NTOT];  // approx min d^2 (float bits)
__device__ unsigned       g_done;
__device__ __nv_bfloat16  g_hi[NTOT * DDIM];
__device__ __half         g_d2[NTOT * NTOT];    // 32 MB approx squared dists

// ---------------- helpers ----------------
__device__ __forceinline__ uint32_t smem_u32(const void* p) {
    uint32_t a;
    asm("{ .reg .u64 t; cvta.to.shared.u64 t, %1; cvt.u32.u64 %0, t; }"
        : "=r"(a) : "l"(p));
    return a;
}
__device__ __forceinline__ void cp16(uint32_t dst, const void* src) {
    asm volatile("cp.async.cg.shared.global [%0], [%1], 16;"
                 :: "r"(dst), "l"(src));
}
#define CP_COMMIT() asm volatile("cp.async.commit_group;" ::: "memory")
#define CP_WAIT2()  asm volatile("cp.async.wait_group 2;" ::: "memory")
#define CP_WAIT1()  asm volatile("cp.async.wait_group 1;" ::: "memory")
#define CP_WAIT0()  asm volatile("cp.async.wait_group 0;" ::: "memory")

__device__ __forceinline__ void ldx4(uint32_t* r, uint32_t addr) {
    asm volatile("ldmatrix.sync.aligned.m8n8.x4.shared.b16 {%0,%1,%2,%3}, [%4];"
                 : "=r"(r[0]), "=r"(r[1]), "=r"(r[2]), "=r"(r[3]) : "r"(addr));
}
__device__ __forceinline__ void mma16816(float* d, const uint32_t* a,
                                         const uint32_t* b) {
    asm volatile(
        "mma.sync.aligned.m16n8k16.row.col.f32.bf16.bf16.f32 "
        "{%0,%1,%2,%3}, {%4,%5,%6,%7}, {%8,%9}, {%0,%1,%2,%3};"
        : "+f"(d[0]), "+f"(d[1]), "+f"(d[2]), "+f"(d[3])
        : "r"(a[0]), "r"(a[1]), "r"(a[2]), "r"(a[3]), "r"(b[0]), "r"(b[1]));
}
__device__ __forceinline__ float clamp_dist(float d2) {
    return fmaxf(sqrtf(fmaxf(d2, 1e-14f)), 1e-7f);
}

// ---------------------------------------------------------------------------
// Kernel 1: per-pair sums of squares, exact positive dist, bf16-hi split,
//           negmin + done-counter reset
// ---------------------------------------------------------------------------
__global__ __launch_bounds__(256)
void prep_kernel(const float* __restrict__ h1,
                 const float* __restrict__ h2) {
    const int wid = threadIdx.x >> 5, lane = threadIdx.x & 31;
    const int r = blockIdx.x * 8 + wid;      // 0..2047
    const float* xr = h1 + (size_t)r * DDIM;
    const float* yr = h2 + (size_t)r * DDIM;

    float s1 = 0.0f, s2 = 0.0f, dt = 0.0f;
    #pragma unroll
    for (int u = 0; u < 4; u++) {
        const int fi = lane + 32 * u;
        float4 xv = ((const float4*)xr)[fi];
        float4 yv = ((const float4*)yr)[fi];
        s1 += xv.x * xv.x + xv.y * xv.y + xv.z * xv.z + xv.w * xv.w;
        s2 += yv.x * yv.x + yv.y * yv.y + yv.z * yv.z + yv.w * yv.w;
        dt += xv.x * yv.x + xv.y * yv.y + xv.z * yv.z + xv.w * yv.w;

        size_t bx = (size_t)r * DDIM + 4 * fi;
        __nv_bfloat162* gx = (__nv_bfloat162*)(g_hi + bx);
        gx[0] = __nv_bfloat162(__float2bfloat16(xv.x), __float2bfloat16(xv.y));
        gx[1] = __nv_bfloat162(__float2bfloat16(xv.z), __float2bfloat16(xv.w));
        __nv_bfloat162* gy = (__nv_bfloat162*)(g_hi + bx + (size_t)NHALF * DDIM);
        gy[0] = __nv_bfloat162(__float2bfloat16(yv.x), __float2bfloat16(yv.y));
        gy[1] = __nv_bfloat162(__float2bfloat16(yv.z), __float2bfloat16(yv.w));
    }

    #pragma unroll
    for (int off = 16; off > 0; off >>= 1) {
        s1 += __shfl_xor_sync(0xffffffffu, s1, off);
        s2 += __shfl_xor_sync(0xffffffffu, s2, off);
        dt += __shfl_xor_sync(0xffffffffu, dt, off);
    }

    if (lane == 0) {
        g_sq[r] = s1;
        g_sq[r + NHALF] = s2;
        float pos = clamp_dist(s1 + s2 - 2.0f * dt);
        g_pos[r] = pos;
        g_pos[r + NHALF] = pos;
        g_negmin_bits[r] = 0x7f800000u;
        g_negmin_bits[r + NHALF] = 0x7f800000u;
        if (r == 0) g_done = 0u;
    }
}

// ---------------------------------------------------------------------------
// async-load one pipeline stage (2 tiles of 128 x 32 bf16: Ah, Bh)
// ---------------------------------------------------------------------------
__device__ __forceinline__ void load_stage(uint32_t smb, int stage,
                                           const __nv_bfloat16* ah,
                                           const __nv_bfloat16* bh,
                                           int k0, int tid) {
    const __nv_bfloat16* srcs[2] = {ah, bh};
    uint32_t base = smb + stage * STAGE_B;
    #pragma unroll
    for (int t = 0; t < 2; t++) {
        #pragma unroll
        for (int i = 0; i < 2; i++) {
            int chunk = tid * 2 + i;       // 0..511
            int r = chunk >> 2;            // 0..127
            int c = chunk & 3;             // 16B chunk within 64B row
            cp16(base + t * TILE_B + r * (TPAD * 2) + c * 16,
                 srcs[t] + (size_t)r * DDIM + k0 + c * 8);
        }
    }
}

// ---------------------------------------------------------------------------
// Kernel 2: hi-only bf16 mma.sync X*X^T (upper triangle), 3-stage pipeline;
// stores approx squared dists (fp16) both orientations + register d^2 minima
// ---------------------------------------------------------------------------
__global__ __launch_bounds__(256, 2)
void gemm_dist_kernel() {
    extern __shared__ char smem[];
    const uint32_t smb = smem_u32(smem);
    const int tid = threadIdx.x;
    const int wid = tid >> 5, lane = tid & 31;

    // decode upper-triangle tile index
    int t = blockIdx.x;
    int bi = 0;
    while (t >= NTILE - bi) { t -= NTILE - bi; bi++; }
    const int bj = bi + t;
    const int row0 = bi * BM;
    const int col0 = bj * BN;
    const bool isdiag = (bi == bj);

    const __nv_bfloat16* Ah_g = g_hi + (size_t)row0 * DDIM;
    const __nv_bfloat16* Bh_g = g_hi + (size_t)col0 * DDIM;

    // warp tile: 32 (M) x 64 (N)
    const int wm = wid & 3, wn = wid >> 2;
    const int m0 = wm * 32, n0 = wn * 64;

    float acc[2][8][4];
    #pragma unroll
    for (int i = 0; i < 2; i++)
        #pragma unroll
        for (int j = 0; j < 8; j++)
            #pragma unroll
            for (int q = 0; q < 4; q++)
                acc[i][j][q] = 0.0f;

    const int arow = (lane & 7) + ((lane >> 3) & 1) * 8;
    const int acol = (lane >> 4) * 8;
    const int brow = (lane & 7) + ((lane >> 4) << 3);
    const int bcol = ((lane >> 3) & 1) * 8;

    load_stage(smb, 0, Ah_g, Bh_g, 0, tid);
    CP_COMMIT();
    load_stage(smb, 1, Ah_g, Bh_g, BK, tid);
    CP_COMMIT();

    for (int it = 0; it < NCHUNK; it++) {
        if (it + 2 < NCHUNK) {
            load_stage(smb, (it + 2) % NSTAGE, Ah_g, Bh_g, (it + 2) * BK, tid);
            CP_COMMIT();
            CP_WAIT2();
        } else if (it + 1 < NCHUNK) {
            CP_WAIT1();
        } else {
            CP_WAIT0();
        }
        __syncthreads();

        const uint32_t Ah = smb + (it % NSTAGE) * STAGE_B;
        const uint32_t Bh = Ah + TILE_B;

        #pragma unroll
        for (int ks = 0; ks < 2; ks++) {
            const int kb = ks * 16;
            uint32_t ahr[2][4];
            #pragma unroll
            for (int mt = 0; mt < 2; mt++) {
                uint32_t off = (uint32_t)(m0 + mt * 16 + arow) * (TPAD * 2)
                             + (kb + acol) * 2;
                ldx4(ahr[mt], Ah + off);
            }
            #pragma unroll
            for (int p = 0; p < 4; p++) {
                uint32_t off = (uint32_t)(n0 + p * 16 + brow) * (TPAD * 2)
                             + (kb + bcol) * 2;
                uint32_t rh[4];
                ldx4(rh, Bh + off);
                uint32_t b0h[2] = {rh[0], rh[1]}, b1h[2] = {rh[2], rh[3]};
                #pragma unroll
                for (int mt = 0; mt < 2; mt++) {
                    mma16816(acc[mt][2 * p],     ahr[mt], b0h);
                    mma16816(acc[mt][2 * p + 1], ahr[mt], b1h);
                }
            }
        }
        __syncthreads();
    }

    // ---------------- epilogue (no sqrt anywhere) ----------------
    const float INF = __int_as_float(0x7f800000);
    const int g = lane >> 2;
    const int cl = (lane & 3) * 2;

    // hoisted norms
    float si[4], sqj[16];
    #pragma unroll
    for (int s = 0; s < 4; s++)
        si[s] = g_sq[row0 + m0 + (s >> 1) * 16 + (s & 1) * 8 + g];
    #pragma unroll
    for (int nt = 0; nt < 8; nt++) {
        sqj[2 * nt]     = g_sq[col0 + n0 + nt * 8 + cl];
        sqj[2 * nt + 1] = g_sq[col0 + n0 + nt * 8 + cl + 1];
    }

    __half* ds = (__half*)smem;
    unsigned* s_rmin = (unsigned*)(smem + SM_MIN);
    unsigned* s_cmin = (unsigned*)(smem + SM_MIN + 512);
    ((unsigned*)(smem + SM_MIN))[tid] = 0x7f800000u;  // init both arrays

    float rowv[4], colv[16];
    #pragma unroll
    for (int s = 0; s < 4; s++) rowv[s] = INF;
    #pragma unroll
    for (int s = 0; s < 16; s++) colv[s] = INF;

    #pragma unroll
    for (int mt = 0; mt < 2; mt++) {
        #pragma unroll
        for (int nt = 0; nt < 8; nt++) {
            float dv[4];
            #pragma unroll
            for (int q = 0; q < 4; q++) {
                const int rs = mt * 2 + (q >> 1);
                const int cs = nt * 2 + (q & 1);
                const int gi = row0 + m0 + mt * 16 + (q >> 1) * 8 + g;
                const int gj = col0 + n0 + nt * 8 + cl + (q & 1);
                float d2 = si[rs] + sqj[cs] - 2.0f * acc[mt][nt][q];
                dv[q] = d2;
                bool excl = (gj == gi) || (gj == (gi ^ NHALF));
                float v = excl ? INF : fmaxf(d2, 0.0f);
                rowv[rs] = fminf(rowv[rs], v);
                colv[cs] = fminf(colv[cs], v);
            }
            // fp16 squared-dist tile entries
            const int rb = m0 + mt * 16 + g;
            const int cb = n0 + nt * 8 + cl;
            *(__half2*)&ds[rb * DS_STRIDE + cb] =
                __floats2half2_rn(dv[0], dv[1]);
            *(__half2*)&ds[(rb + 8) * DS_STRIDE + cb] =
                __floats2half2_rn(dv[2], dv[3]);
        }
    }

    // reduce rows over cl (xor 1,2), cols over g (xor 4,8,16)
    #pragma unroll
    for (int off = 1; off <= 2; off <<= 1)
        #pragma unroll
        for (int s = 0; s < 4; s++)
            rowv[s] = fminf(rowv[s], __shfl_xor_sync(0xffffffffu, rowv[s], off));
    #pragma unroll
    for (int off = 4; off <= 16; off <<= 1)
        #pragma unroll
        for (int s = 0; s < 16; s++)
            colv[s] = fminf(colv[s], __shfl_xor_sync(0xffffffffu, colv[s], off));

    __syncthreads();
    if ((lane & 3) == 0) {
        #pragma unroll
        for (int s = 0; s < 4; s++)
            atomicMin(&s_rmin[m0 + (s >> 1) * 16 + (s & 1) * 8 + g],
                      __float_as_uint(rowv[s]));
    }
    if (lane < 4) {
        #pragma unroll
        for (int s = 0; s < 16; s++)
            atomicMin(&s_cmin[n0 + (s >> 1) * 8 + cl + (s & 1)],
                      __float_as_uint(colv[s]));
    }
    __syncthreads();

    // global stores: row block + approx-min atomics
    {
        const int rb = tid >> 1, seg = tid & 1;
        const uint4* src = (const uint4*)&ds[rb * DS_STRIDE + seg * 64];
        uint4* dst = (uint4*)&g_d2[(size_t)(row0 + rb) * NTOT + col0 + seg * 64];
        #pragma unroll
        for (int q = 0; q < 8; q++) dst[q] = src[q];
    }
    if (!isdiag) {
        const int c = tid >> 1, seg = tid & 1;
        __half v[64];
        #pragma unroll 8
        for (int k = 0; k < 64; k++)
            v[k] = ds[(seg * 64 + k) * DS_STRIDE + c];
        uint4* dst = (uint4*)&g_d2[(size_t)(col0 + c) * NTOT + row0 + seg * 64];
        const uint4* sv = (const uint4*)v;
        #pragma unroll
        for (int q = 0; q < 8; q++) dst[q] = sv[q];
    }
    if (tid < 128) {
        atomicMin(&g_negmin_bits[row0 + tid], s_rmin[tid]);
    } else if (!isdiag) {
        atomicMin(&g_negmin_bits[col0 + tid - 128], s_cmin[tid - 128]);
    }
}

// ---------------------------------------------------------------------------
// Kernel 3: refine — d^2-space vectorized candidate pass + exact recompute
//           + fused finalize.  grid RGRID x 256 (8 warps); warp = one row
// ---------------------------------------------------------------------------
__global__ __launch_bounds__(256)
void refine_kernel(const float* __restrict__ h1,
                   const float* __restrict__ h2,
                   float* __restrict__ out) {
    const int wid = threadIdx.x >> 5, lane = threadIdx.x & 31;
    const int r = blockIdx.x * 8 + wid;          // 0..4095
    const int partner = r ^ NHALF;
    const float INF = __int_as_float(0x7f800000);

    const float d2min = fmaxf(__uint_as_float(g_negmin_bits[r]), 0.0f);
    const float tdist = sqrtf(d2min) + MARGIN;
    const float thresh2 = tdist * tdist + 2.0f;    // pad for fp16 d^2 rounding
    const __half hthresh2 = __float2half_rn(thresh2 + 1.0f);

    const __half* row = g_d2 + (size_t)r * NTOT;
    const uint4* row4 = (const uint4*)row;

    // preload this row's fp32 data (16 dims per lane)
    const float* xr = (r < NHALF) ? h1 + (size_t)r * DDIM
                                  : h2 + (size_t)(r - NHALF) * DDIM;
    float4 x4[4];
    #pragma unroll
    for (int q = 0; q < 4; q++)
        x4[q] = ((const float4*)xr)[lane * 4 + q];
    const float sqr = g_sq[r];

    float ex = INF;
    #pragma unroll 4
    for (int it = 0; it < 16; it++) {
        const int idx = it * 32 + lane;          // uint4 index
        const int j0 = idx * 8;
        uint4 u = row4[idx];
        const __half2* hp = (const __half2*)&u;

        __half2 mm = __hmin2(__hmin2(hp[0], hp[1]), __hmin2(hp[2], hp[3]));
        __half m = __hmin(__low2half(mm), __high2half(mm));
        unsigned cmask = 0;
        if (__hle(m, hthresh2)) {
            #pragma unroll
            for (int h = 0; h < 4; h++) {
                float2 f = __half22float2(hp[h]);
                const int j = j0 + 2 * h;
                if (f.x <= thresh2 && j != r && j != partner)
                    cmask |= 1u << (2 * h);
                if (f.y <= thresh2 && j + 1 != r && j + 1 != partner)
                    cmask |= 1u << (2 * h + 1);
            }
        }
        unsigned act = __ballot_sync(0xffffffffu, cmask != 0);
        while (act) {
            const int b = __ffs(act) - 1;
            act &= act - 1;
            unsigned pb = __shfl_sync(0xffffffffu, cmask, b);
            const int jb = __shfl_sync(0xffffffffu, j0, b);
            while (pb) {
                const int s = __ffs(pb) - 1;
                pb &= pb - 1;
                const int j = jb + s;
                const float* yr = (j < NHALF) ? h1 + (size_t)j * DDIM
                                              : h2 + (size_t)(j - NHALF) * DDIM;
                float dot = 0.0f;
                #pragma unroll
                for (int q = 0; q < 4; q++) {
                    float4 yv = ((const float4*)yr)[lane * 4 + q];
                    dot += x4[q].x * yv.x + x4[q].y * yv.y
                         + x4[q].z * yv.z + x4[q].w * yv.w;
                }
                #pragma unroll
                for (int off = 16; off > 0; off >>= 1)
                    dot += __shfl_xor_sync(0xffffffffu, dot, off);
                ex = fminf(ex, clamp_dist(sqr + g_sq[j] - 2.0f * dot));
            }
        }
    }
    if (lane == 0) g_neg[r] = ex;

    // ---- fused finalize: last block to finish reduces everything ----
    __shared__ int s_last;
    __threadfence();
    __syncthreads();
    if (threadIdx.x == 0) {
        unsigned v = atomicAdd(&g_done, 1u);
        s_last = (v == RGRID - 1) ? 1 : 0;
    }
    __syncthreads();
    if (!s_last) return;

    const int t = threadIdx.x;
    float sumdiff = 0.0f, sumrel = 0.0f, sumsq = 0.0f;
    int nrel = 0, good = 0;
    #pragma unroll 4
    for (int i = t; i < NTOT; i += 256) {
        float diff = g_pos[i] - g_neg[i];
        float tl = fmaxf(diff + 0.1f, 0.0f);
        sumdiff += diff;
        if (tl > 1e-5f) { sumrel += tl; nrel++; }
        if (tl < 1e-5f) good++;
        sumsq += g_sq[i];
    }
    #pragma unroll
    for (int off = 16; off > 0; off >>= 1) {
        sumdiff += __shfl_xor_sync(0xffffffffu, sumdiff, off);
        sumrel  += __shfl_xor_sync(0xffffffffu, sumrel, off);
        sumsq   += __shfl_xor_sync(0xffffffffu, sumsq, off);
        nrel    += __shfl_xor_sync(0xffffffffu, nrel, off);
        good    += __shfl_xor_sync(0xffffffffu, good, off);
    }
    __shared__ float s_diff[8], s_rel[8], s_sq[8];
    __shared__ int   s_nrel[8], s_good[8];
    if (lane == 0) {
        s_diff[wid] = sumdiff; s_rel[wid] = sumrel; s_sq[wid] = sumsq;
        s_nrel[wid] = nrel;    s_good[wid] = good;
    }
    __syncthreads();
    if (t == 0) {
        float td = 0, tr = 0, tq = 0; int tn = 0, tg = 0;
        #pragma unroll
        for (int w = 0; w < 8; w++) {
            td += s_diff[w]; tr += s_rel[w]; tq += s_sq[w];
            tn += s_nrel[w]; tg += s_good[w];
        }
        int n_rel = tn > 0 ? tn : 1;
        out[0] = tr / (float)n_rel;
        out[1] = td / (float)NTOT;
        out[2] = (float)tg;
        out[3] = (float)(NTOT - tg);
        out[4] = sqrtf(tq / (float)NTOT);
    }
}

// ---------------------------------------------------------------------------
extern "C" void kernel_launch(void* const* d_in, const int* in_sizes, int n_in,
                              void* d_out, int out_size) {
    const float* h1 = (const float*)d_in[0];
    const float* h2 = (const float*)d_in[1];
    float* out = (float*)d_out;

    cudaFuncSetAttribute(gemm_dist_kernel,
                         cudaFuncAttributeMaxDynamicSharedMemorySize, SM_TOTAL);

    prep_kernel<<<NHALF / 8, 256>>>(h1, h2);
    gemm_dist_kernel<<<NBLK, 256, SM_TOTAL>>>();
    refine_kernel<<<RGRID, 256>>>(h1, h2, out);
}